// round 12
// baseline (speedup 1.0000x reference)
#include <cuda_runtime.h>
#include <cfloat>

// ============================================================================
// Converged at the HBM roofline (~6.4-6.6 TB/s mixed R/W on GB300).
// Structure: 512-thr register-staged single pass; phase 2a = pure store
// stream (dense STG issue, measured DRAM 83.4%); phase 2b = separate sum
// loop on NORMALIZED values in the tid-strided order that reproduces the
// reference keypoints exactly (rel_err 5.85e-8 in prior rounds).
// ============================================================================

constexpr int W_DIM   = 128;
constexpr int HW      = 128 * 128;     // 16384 elements per (b,c) plane
constexpr int THREADS = 512;
constexpr int V4      = HW / 4;        // 4096 float4 per plane
constexpr int PER     = V4 / THREADS;  // 8 float4 per thread

__device__ __forceinline__ float warp_sum(float v) {
    #pragma unroll
    for (int o = 16; o > 0; o >>= 1) v += __shfl_down_sync(0xffffffffu, v, o);
    return v;
}
__device__ __forceinline__ float warp_min(float v) {
    #pragma unroll
    for (int o = 16; o > 0; o >>= 1) v = fminf(v, __shfl_down_sync(0xffffffffu, v, o));
    return v;
}
__device__ __forceinline__ float warp_max(float v) {
    #pragma unroll
    for (int o = 16; o > 0; o >>= 1) v = fmaxf(v, __shfl_down_sync(0xffffffffu, v, o));
    return v;
}

__global__ __launch_bounds__(THREADS)
void hm2kp_kernel(const float* __restrict__ in,
                  float* __restrict__ map_out,
                  float* __restrict__ kp_out,
                  float* __restrict__ zeta_out)
{
    __shared__ float s_r0[16], s_r1[16], s_r2[16];
    __shared__ float s_bmin, s_rcp;

    const int bc   = blockIdx.x;
    const int tid  = threadIdx.x;
    const int lane = tid & 31;
    const int wid  = tid >> 5;

    const float4* __restrict__ inp  = reinterpret_cast<const float4*>(in) + (size_t)bc * V4;
    float4* __restrict__       outp = reinterpret_cast<float4*>(map_out) + (size_t)bc * V4;

    // ---- Phase 1: stage whole plane in registers; min/max ----
    float4 v[PER];
    float lmin = FLT_MAX, lmax = -FLT_MAX;
    #pragma unroll
    for (int i = 0; i < PER; ++i) {
        v[i] = __ldcs(&inp[tid + i * THREADS]);
        lmin = fminf(lmin, fminf(fminf(v[i].x, v[i].y), fminf(v[i].z, v[i].w)));
        lmax = fmaxf(lmax, fmaxf(fmaxf(v[i].x, v[i].y), fmaxf(v[i].z, v[i].w)));
    }

    // ---- Block reduce min/max (16 warps) ----
    lmin = warp_min(lmin);
    lmax = warp_max(lmax);
    if (lane == 0) { s_r0[wid] = lmin; s_r1[wid] = lmax; }
    __syncthreads();
    if (wid == 0) {
        float m0 = (lane < 16) ? s_r0[lane] :  FLT_MAX;
        float m1 = (lane < 16) ? s_r1[lane] : -FLT_MAX;
        m0 = warp_min(m0);
        m1 = warp_max(m1);
        if (lane == 0) { s_bmin = m0; s_rcp = 1.0f / m1; }  // ref divides by max (not max-min)
    }
    __syncthreads();

    const float bmin = s_bmin;
    const float rcp  = s_rcp;

    // ---- Phase 2a: PURE normalize + store stream. No accumulation in the
    //      loop: STG.128s issue back-to-back (dense store issue, R11). ----
    #pragma unroll
    for (int i = 0; i < PER; ++i) {
        const int i4 = tid + i * THREADS;
        float4 o;
        o.x = (v[i].x - bmin) * rcp;
        o.y = (v[i].y - bmin) * rcp;
        o.z = (v[i].z - bmin) * rcp;
        o.w = (v[i].w - bmin) * rcp;
        __stcs(&outp[i4], o);
    }

    // ---- Phase 2b: recompute normalized values from live regs, accumulate
    //      the three sums in the exact tid-strided order (exact numerics).
    //      Runs while the store stream drains; FMA pipes are ~12% busy. ----
    float sum = 0.f, sx = 0.f, sy = 0.f;
    #pragma unroll
    for (int i = 0; i < PER; ++i) {
        const int i4 = tid + i * THREADS;
        const float m0 = (v[i].x - bmin) * rcp;
        const float m1 = (v[i].y - bmin) * rcp;
        const float m2 = (v[i].z - bmin) * rcp;
        const float m3 = (v[i].w - bmin) * rcp;

        const int base = i4 << 2;                     // element index in plane
        const float x0 = (float)(base & (W_DIM - 1));
        const float yy = (float)(base >> 7);          // row (constant per float4)

        const float s4 = (m0 + m1) + (m2 + m3);
        sum += s4;
        sx  += m0 * x0 + m1 * (x0 + 1.f) + m2 * (x0 + 2.f) + m3 * (x0 + 3.f);
        sy  += s4 * yy;
    }

    // ---- Block reduce the three sums (16 warps) ----
    sum = warp_sum(sum);
    sx  = warp_sum(sx);
    sy  = warp_sum(sy);
    if (lane == 0) { s_r0[wid] = sum; s_r1[wid] = sx; s_r2[wid] = sy; }
    __syncthreads();
    if (wid == 0) {
        float a = (lane < 16) ? s_r0[lane] : 0.f;
        float b = (lane < 16) ? s_r1[lane] : 0.f;
        float c = (lane < 16) ? s_r2[lane] : 0.f;
        a = warp_sum(a);
        b = warp_sum(b);
        c = warp_sum(c);
        if (lane == 0) {
            kp_out[(size_t)bc * 2 + 0] = rintf(b / a);  // round(get_kp_x / zeta)
            kp_out[(size_t)bc * 2 + 1] = rintf(c / a);  // round(get_kp_y / zeta)
            zeta_out[bc] = a;
        }
    }
}

extern "C" void kernel_launch(void* const* d_in, const int* in_sizes, int n_in,
                              void* d_out, int out_size)
{
    const float* in = (const float*)d_in[0];
    const int total  = in_sizes[0];        // B*C*H*W
    const int planes = total / HW;         // B*C = 6400

    float* map  = (float*)d_out;                       // [B,C,H,W]
    float* kp   = map + (size_t)total;                 // [B,C,2]
    float* zeta = kp + (size_t)planes * 2;             // [B,C]

    hm2kp_kernel<<<planes, THREADS>>>(in, map, kp, zeta);
}

// round 13
// speedup vs baseline: 1.0013x; 1.0013x over previous
#include <cuda_runtime.h>
#include <cfloat>

// ============================================================================
// FINAL KERNEL — converged at the HBM roofline (12-round series).
//
// Perf: kernel 119.3 us, 6.57 TB/s combined R/W = measured LTS ceiling for a
// 50/50 read/write stream on GB300 (sm_103a). Traffic is irreducible:
// 419 MB read + 419 MB write. All structural alternatives regressed:
// persistent grid (-15%), TMA pipe x2/x3 (-20/-22%), warp-granular (spill),
// two-pass L2 re-read (-4%). Occupancy 45-98% proven non-binding.
//
// Numerics: rel_err 5.85e-8 (exact reference keypoints). Load-bearing
// choices: (a) sums computed on NORMALIZED values (analytic raw-sum
// transform flips rintf at .5 boundaries -> 1.4e-4), (b) 512-thread,
// PER=8, tid-strided accumulation ordering. Do not change either.
//
// Structure: phase 2a is a PURE store stream (dense STG.128 issue — worth
// ~1 us over interleaved accumulation); phase 2b recomputes normalized
// values from live registers for the reductions (FMA pipes ~12% busy, free).
// ============================================================================

constexpr int W_DIM   = 128;
constexpr int HW      = 128 * 128;     // 16384 elements per (b,c) plane
constexpr int THREADS = 512;
constexpr int V4      = HW / 4;        // 4096 float4 per plane
constexpr int PER     = V4 / THREADS;  // 8 float4 per thread

__device__ __forceinline__ float warp_sum(float v) {
    #pragma unroll
    for (int o = 16; o > 0; o >>= 1) v += __shfl_down_sync(0xffffffffu, v, o);
    return v;
}
__device__ __forceinline__ float warp_min(float v) {
    #pragma unroll
    for (int o = 16; o > 0; o >>= 1) v = fminf(v, __shfl_down_sync(0xffffffffu, v, o));
    return v;
}
__device__ __forceinline__ float warp_max(float v) {
    #pragma unroll
    for (int o = 16; o > 0; o >>= 1) v = fmaxf(v, __shfl_down_sync(0xffffffffu, v, o));
    return v;
}

__global__ __launch_bounds__(THREADS)
void hm2kp_kernel(const float* __restrict__ in,
                  float* __restrict__ map_out,
                  float* __restrict__ kp_out,
                  float* __restrict__ zeta_out)
{
    __shared__ float s_r0[16], s_r1[16], s_r2[16];
    __shared__ float s_bmin, s_rcp;

    const int bc   = blockIdx.x;
    const int tid  = threadIdx.x;
    const int lane = tid & 31;
    const int wid  = tid >> 5;

    const float4* __restrict__ inp  = reinterpret_cast<const float4*>(in) + (size_t)bc * V4;
    float4* __restrict__       outp = reinterpret_cast<float4*>(map_out) + (size_t)bc * V4;

    // ---- Phase 1: stage whole plane in registers; min/max ----
    float4 v[PER];
    float lmin = FLT_MAX, lmax = -FLT_MAX;
    #pragma unroll
    for (int i = 0; i < PER; ++i) {
        v[i] = __ldcs(&inp[tid + i * THREADS]);
        lmin = fminf(lmin, fminf(fminf(v[i].x, v[i].y), fminf(v[i].z, v[i].w)));
        lmax = fmaxf(lmax, fmaxf(fmaxf(v[i].x, v[i].y), fmaxf(v[i].z, v[i].w)));
    }

    // ---- Block reduce min/max (16 warps) ----
    lmin = warp_min(lmin);
    lmax = warp_max(lmax);
    if (lane == 0) { s_r0[wid] = lmin; s_r1[wid] = lmax; }
    __syncthreads();
    if (wid == 0) {
        float m0 = (lane < 16) ? s_r0[lane] :  FLT_MAX;
        float m1 = (lane < 16) ? s_r1[lane] : -FLT_MAX;
        m0 = warp_min(m0);
        m1 = warp_max(m1);
        if (lane == 0) { s_bmin = m0; s_rcp = 1.0f / m1; }  // ref divides by max (not max-min)
    }
    __syncthreads();

    const float bmin = s_bmin;
    const float rcp  = s_rcp;

    // ---- Phase 2a: PURE normalize + store stream (dense STG.128 issue) ----
    #pragma unroll
    for (int i = 0; i < PER; ++i) {
        const int i4 = tid + i * THREADS;
        float4 o;
        o.x = (v[i].x - bmin) * rcp;
        o.y = (v[i].y - bmin) * rcp;
        o.z = (v[i].z - bmin) * rcp;
        o.w = (v[i].w - bmin) * rcp;
        __stcs(&outp[i4], o);
    }

    // ---- Phase 2b: recompute normalized values from live regs; accumulate
    //      the three sums in the exact tid-strided order (exact numerics). ----
    float sum = 0.f, sx = 0.f, sy = 0.f;
    #pragma unroll
    for (int i = 0; i < PER; ++i) {
        const int i4 = tid + i * THREADS;
        const float m0 = (v[i].x - bmin) * rcp;
        const float m1 = (v[i].y - bmin) * rcp;
        const float m2 = (v[i].z - bmin) * rcp;
        const float m3 = (v[i].w - bmin) * rcp;

        const int base = i4 << 2;                     // element index in plane
        const float x0 = (float)(base & (W_DIM - 1));
        const float yy = (float)(base >> 7);          // row (constant per float4)

        const float s4 = (m0 + m1) + (m2 + m3);
        sum += s4;
        sx  += m0 * x0 + m1 * (x0 + 1.f) + m2 * (x0 + 2.f) + m3 * (x0 + 3.f);
        sy  += s4 * yy;
    }

    // ---- Block reduce the three sums (16 warps) ----
    sum = warp_sum(sum);
    sx  = warp_sum(sx);
    sy  = warp_sum(sy);
    if (lane == 0) { s_r0[wid] = sum; s_r1[wid] = sx; s_r2[wid] = sy; }
    __syncthreads();
    if (wid == 0) {
        float a = (lane < 16) ? s_r0[lane] : 0.f;
        float b = (lane < 16) ? s_r1[lane] : 0.f;
        float c = (lane < 16) ? s_r2[lane] : 0.f;
        a = warp_sum(a);
        b = warp_sum(b);
        c = warp_sum(c);
        if (lane == 0) {
            kp_out[(size_t)bc * 2 + 0] = rintf(b / a);  // round(get_kp_x / zeta)
            kp_out[(size_t)bc * 2 + 1] = rintf(c / a);  // round(get_kp_y / zeta)
            zeta_out[bc] = a;
        }
    }
}

extern "C" void kernel_launch(void* const* d_in, const int* in_sizes, int n_in,
                              void* d_out, int out_size)
{
    const float* in = (const float*)d_in[0];
    const int total  = in_sizes[0];        // B*C*H*W
    const int planes = total / HW;         // B*C = 6400

    float* map  = (float*)d_out;                       // [B,C,H,W]
    float* kp   = map + (size_t)total;                 // [B,C,2]
    float* zeta = kp + (size_t)planes * 2;             // [B,C]

    hm2kp_kernel<<<planes, THREADS>>>(in, map, kp, zeta);
}